// round 4
// baseline (speedup 1.0000x reference)
#include <cuda_runtime.h>
#include <cstdint>

#define D_FEAT      128
#define N_EDGES_MAX 50008

// Scratch: segment start offsets (d_seg_start[e] = first flat index with seg id >= e)
__device__ int d_seg_start[N_EDGES_MAX + 1];

// ---------------------------------------------------------------------------
// Kernel 1: run-boundary detection on the sorted segment_ids (int32).
// ---------------------------------------------------------------------------
__global__ void offsets_kernel(const int* __restrict__ seg_ids,
                               int flat, int n_edges) {
    int i = blockIdx.x * blockDim.x + threadIdx.x;
    if (i >= flat) return;
    int cur  = __ldg(&seg_ids[i]);
    int prev = (i == 0) ? -1 : __ldg(&seg_ids[i - 1]);
    for (int e = prev + 1; e <= cur; e++)       // usually 0 or 1 iterations
        d_seg_start[e] = i;
    if (i == flat - 1) {
        for (int e = cur + 1; e <= n_edges; e++)
            d_seg_start[e] = flat;
    }
}

// ---------------------------------------------------------------------------
// Kernel 2: warp-per-segment ragged segment-max, SCALAR row loads.
// Lane l owns features {l, l+32, l+64, l+96}. Each member row is fetched with
// 4 independent LDG.32 instructions, each touching exactly ONE 128B line
// (1 L1tex wavefront @ 1.0 cyc, no within-LDG replays) instead of one LDG.128
// spanning 4 lines (1 + 3 replays @ 2.07 cyc). Index loads are clamped to
// avoid a separate dependent "first index" load and lane divergence.
// ---------------------------------------------------------------------------
__global__ void __launch_bounds__(256)
seg_max_kernel(const float* __restrict__ emb,       // [N_NODES * 128]
               const int* __restrict__ node_idx,
               float* __restrict__ out,             // [n_edges * 128]
               int n_edges) {
    int gwarp = (blockIdx.x * blockDim.x + threadIdx.x) >> 5;
    int lane  = threadIdx.x & 31;
    if (gwarp >= n_edges) return;

    int start = d_seg_start[gwarp];
    int end   = d_seg_start[gwarp + 1];

    float* o = out + (size_t)gwarp * D_FEAT + lane;

    if (start >= end) {                     // empty segment -> zeros
        o[0]  = 0.f;
        o[32] = 0.f;
        o[64] = 0.f;
        o[96] = 0.f;
        return;
    }

    const float NEG = -3.402823466e+38f;
    float a0 = NEG, a1 = NEG, a2 = NEG, a3 = NEG;

    const float* embl = emb + lane;
    int last = end - 1;

    for (int base = start; base < end; base += 32) {
        // clamped coalesced index fetch (idempotent max -> duplicates are free)
        int li = base + lane;
        int nd_l = __ldg(&node_idx[li <= last ? li : last]);
        int cnt = end - base;
        if (cnt > 32) cnt = 32;

        #pragma unroll 4
        for (int j = 0; j < cnt; j++) {
            int nd = __shfl_sync(0xffffffffu, nd_l, j);
            const float* r = embl + (size_t)nd * D_FEAT;
            float v0 = __ldg(r);
            float v1 = __ldg(r + 32);
            float v2 = __ldg(r + 64);
            float v3 = __ldg(r + 96);
            a0 = fmaxf(a0, v0);
            a1 = fmaxf(a1, v1);
            a2 = fmaxf(a2, v2);
            a3 = fmaxf(a3, v3);
        }
    }

    o[0]  = a0;
    o[32] = a1;
    o[64] = a2;
    o[96] = a3;
}

// ---------------------------------------------------------------------------
// Launch
// inputs: emb_table f32 [100000,128], node_idx i32 [1.6M],
//         segment_ids i32 [1.6M], num_segments scalar
// output: f32 [50000,128]
// ---------------------------------------------------------------------------
extern "C" void kernel_launch(void* const* d_in, const int* in_sizes, int n_in,
                              void* d_out, int out_size) {
    const float* emb      = (const float*)d_in[0];
    const int*   node_idx = (const int*)d_in[1];
    const int*   seg_ids  = (const int*)d_in[2];
    float*       out      = (float*)d_out;

    int flat    = in_sizes[1];            // 1,600,000
    int n_edges = out_size / D_FEAT;      // 50,000

    {
        int threads = 256;
        int blocks  = (flat + threads - 1) / threads;
        offsets_kernel<<<blocks, threads>>>(seg_ids, flat, n_edges);
    }
    {
        int threads = 256;                 // 8 warps = 8 segments / block
        int blocks  = (n_edges * 32 + threads - 1) / threads;
        seg_max_kernel<<<blocks, threads>>>(emb, node_idx, out, n_edges);
    }
}